// round 1
// baseline (speedup 1.0000x reference)
#include <cuda_runtime.h>

#define NN   50000
#define FIN  256
#define HD   128
#define SS   50
#define GG   1000          // NN/SS
#define EMAX 1600000
#define NBLK ((NN + 255) / 256)   // 196

// ---------------- scratch (static device globals; no allocation) ----------------
__device__ __align__(16) int   g_deg[NN];
__device__ __align__(16) float g_dinv[NN];
__device__ __align__(16) int   g_rowptr[NN + 1];
__device__ __align__(16) int   g_fill[NN];
__device__ __align__(16) int   g_srcs[EMAX];
__device__ __align__(16) float g_norm[EMAX];
__device__ __align__(16) float g_xw[NN * HD];
__device__ __align__(16) float g_h1[NN * HD];
__device__ __align__(16) float g_hw[NN * HD];
__device__ __align__(16) int   g_part[256];

// ---------------- degree / CSR build ----------------
__global__ void k_zero_deg() {
    int i = blockIdx.x * blockDim.x + threadIdx.x;
    if (i < NN) g_deg[i] = 0;
}

__global__ void k_count(const int* __restrict__ dst, int Ecnt) {
    int e = blockIdx.x * blockDim.x + threadIdx.x;
    if (e < Ecnt) atomicAdd(&g_deg[dst[e]], 1);
}

__global__ void k_dinv() {
    int i = blockIdx.x * blockDim.x + threadIdx.x;
    if (i < NN) g_dinv[i] = rsqrtf((float)g_deg[i] + 1.0f);  // +1 self-loop
}

// block-local inclusive scan of g_deg -> g_rowptr[i+1] (partial), block totals -> g_part
__global__ void k_scan1() {
    __shared__ int sh[256];
    int tid = threadIdx.x;
    int i = blockIdx.x * 256 + tid;
    int v = (i < NN) ? g_deg[i] : 0;
    sh[tid] = v;
    __syncthreads();
    #pragma unroll
    for (int o = 1; o < 256; o <<= 1) {
        int t = (tid >= o) ? sh[tid - o] : 0;
        __syncthreads();
        sh[tid] += t;
        __syncthreads();
    }
    if (i < NN) g_rowptr[i + 1] = sh[tid];
    if (tid == 255) g_part[blockIdx.x] = sh[255];
}

// scan block totals (single block)
__global__ void k_scan2() {
    __shared__ int sh[256];
    int tid = threadIdx.x;
    int v = (tid < NBLK) ? g_part[tid] : 0;
    sh[tid] = v;
    __syncthreads();
    #pragma unroll
    for (int o = 1; o < 256; o <<= 1) {
        int t = (tid >= o) ? sh[tid - o] : 0;
        __syncthreads();
        sh[tid] += t;
        __syncthreads();
    }
    g_part[tid] = sh[tid];
}

__global__ void k_scan3() {
    int i = blockIdx.x * blockDim.x + threadIdx.x;
    if (i < NN) {
        int b = i >> 8;
        int off = (b > 0) ? g_part[b - 1] : 0;
        g_rowptr[i + 1] += off;
        if (i == 0) g_rowptr[0] = 0;
    }
}

__global__ void k_fillinit() {
    int i = blockIdx.x * blockDim.x + threadIdx.x;
    if (i < NN) g_fill[i] = g_rowptr[i];
}

__global__ void k_fill(const int* __restrict__ src, const int* __restrict__ dst, int Ecnt) {
    int e = blockIdx.x * blockDim.x + threadIdx.x;
    if (e < Ecnt) {
        int s = src[e], d = dst[e];
        int p = atomicAdd(&g_fill[d], 1);
        g_srcs[p] = s;
        g_norm[p] = g_dinv[s] * g_dinv[d];
    }
}

// ---------------- generic GEMM: C[M,128] = A[M,K] @ B[K,128] ----------------
// BM=64, BN=128, BK=16; 256 threads, each computes 8x4.
__global__ void gemm_k(const float* __restrict__ A, const float* __restrict__ B,
                       float* __restrict__ C, int M, int K) {
    __shared__ float As[64][16];
    __shared__ float Bs[16][128];
    int tid = threadIdx.x;
    int tx = tid & 31, ty = tid >> 5;
    int r0 = blockIdx.x * 64;

    float acc[8][4];
    #pragma unroll
    for (int i = 0; i < 8; i++)
        #pragma unroll
        for (int j = 0; j < 4; j++) acc[i][j] = 0.0f;

    for (int kt = 0; kt < K; kt += 16) {
        // As: 1024 floats, one float4 per thread
        {
            int l = tid * 4;
            int row = l >> 4, col = l & 15;
            int gr = r0 + row;
            float4 v = make_float4(0.f, 0.f, 0.f, 0.f);
            if (gr < M) v = *(const float4*)&A[(long)gr * K + kt + col];
            *(float4*)&As[row][col] = v;
        }
        // Bs: 2048 floats, two float4 per thread
        #pragma unroll
        for (int it = 0; it < 2; it++) {
            int l = (tid + it * 256) * 4;
            int row = l >> 7, col = l & 127;
            *(float4*)&Bs[row][col] = *(const float4*)&B[(kt + row) * 128 + col];
        }
        __syncthreads();

        #pragma unroll
        for (int k = 0; k < 16; k++) {
            float4 bv = *(float4*)&Bs[k][tx * 4];
            #pragma unroll
            for (int i = 0; i < 8; i++) {
                float a = As[ty * 8 + i][k];
                acc[i][0] = fmaf(a, bv.x, acc[i][0]);
                acc[i][1] = fmaf(a, bv.y, acc[i][1]);
                acc[i][2] = fmaf(a, bv.z, acc[i][2]);
                acc[i][3] = fmaf(a, bv.w, acc[i][3]);
            }
        }
        __syncthreads();
    }

    #pragma unroll
    for (int i = 0; i < 8; i++) {
        int r = r0 + ty * 8 + i;
        if (r < M) {
            float4 v = make_float4(acc[i][0], acc[i][1], acc[i][2], acc[i][3]);
            *(float4*)&C[(long)r * 128 + tx * 4] = v;
        }
    }
}

// ---------------- GCN aggregation: O[n] = sum_{s in N(n)} norm*T[s] + dinv(n)^2*T[n] + b ----------------
// one warp per node, float4 per lane
__global__ void agg_k(const float* __restrict__ T, const float* __restrict__ bias,
                      float* __restrict__ O, int relu) {
    int warp = threadIdx.x >> 5, lane = threadIdx.x & 31;
    int node = blockIdx.x * 8 + warp;
    if (node >= NN) return;

    const float4* Tv = (const float4*)T;
    float di = g_dinv[node];
    float w0 = di * di;
    float4 a = Tv[node * 32 + lane];
    float4 acc;
    acc.x = w0 * a.x; acc.y = w0 * a.y; acc.z = w0 * a.z; acc.w = w0 * a.w;

    int b = g_rowptr[node], e = g_rowptr[node + 1];
    for (int j = b; j < e; j++) {
        int s = __ldg(&g_srcs[j]);
        float w = __ldg(&g_norm[j]);
        float4 v = Tv[s * 32 + lane];
        acc.x = fmaf(w, v.x, acc.x);
        acc.y = fmaf(w, v.y, acc.y);
        acc.z = fmaf(w, v.z, acc.z);
        acc.w = fmaf(w, v.w, acc.w);
    }
    float4 bb = ((const float4*)bias)[lane];
    acc.x += bb.x; acc.y += bb.y; acc.z += bb.z; acc.w += bb.w;
    if (relu) {
        acc.x = fmaxf(acc.x, 0.f); acc.y = fmaxf(acc.y, 0.f);
        acc.z = fmaxf(acc.z, 0.f); acc.w = fmaxf(acc.w, 0.f);
    }
    ((float4*)O)[node * 32 + lane] = acc;
}

// ---------------- pooled head: out[g,j] = sum_k emb[g*6400+k]*Wl[k,j] + bl[j] ----------------
// 8 groups per block, 256 threads; BK=32 chunks of Wl cached in smem
__global__ void pool_k(const float* __restrict__ emb, const float* __restrict__ Wl,
                       const float* __restrict__ bl, float* __restrict__ out) {
    __shared__ float sW[32][128];
    __shared__ float sE[8][33];
    int tid = threadIdx.x;
    int g0 = blockIdx.x * 8;
    int jj = tid & 127, half = tid >> 7;

    float acc[4] = {0.f, 0.f, 0.f, 0.f};

    for (int k0 = 0; k0 < SS * HD; k0 += 32) {
        // Wl tile: 4096 floats = 4 float4 per thread
        #pragma unroll
        for (int it = 0; it < 4; it++) {
            int l = (tid + it * 256) * 4;
            int row = l >> 7, col = l & 127;
            *(float4*)&sW[row][col] = *(const float4*)&Wl[(k0 + row) * 128 + col];
        }
        // emb tile: 8x32 = 256 floats, one per thread
        {
            int r = tid >> 5, c = tid & 31;
            sE[r][c] = emb[(g0 + r) * 6400 + k0 + c];
        }
        __syncthreads();

        #pragma unroll
        for (int kk = 0; kk < 32; kk++) {
            float w = sW[kk][jj];
            #pragma unroll
            for (int gg = 0; gg < 4; gg++)
                acc[gg] = fmaf(sE[half * 4 + gg][kk], w, acc[gg]);
        }
        __syncthreads();
    }

    float bv = bl[jj];
    #pragma unroll
    for (int gg = 0; gg < 4; gg++)
        out[(g0 + half * 4 + gg) * 128 + jj] = acc[gg] + bv;
}

// ---------------- launch ----------------
extern "C" void kernel_launch(void* const* d_in, const int* in_sizes, int n_in,
                              void* d_out, int out_size) {
    const float* x  = (const float*)d_in[0];
    const float* W1 = (const float*)d_in[1];
    const float* b1 = (const float*)d_in[2];
    const float* W2 = (const float*)d_in[3];
    const float* b2 = (const float*)d_in[4];
    const float* Wl = (const float*)d_in[5];
    const float* bl = (const float*)d_in[6];
    const int*   ei = (const int*)d_in[7];

    int Ecnt = in_sizes[7] / 2;
    const int* src = ei;
    const int* dst = ei + Ecnt;

    float* out = (float*)d_out;            // [1000,128]
    float* emb = out + GG * HD;            // [50000,128]

    int eb = (Ecnt + 255) / 256;

    // CSR build + normalization
    k_zero_deg<<<NBLK, 256>>>();
    k_count<<<eb, 256>>>(dst, Ecnt);
    k_dinv<<<NBLK, 256>>>();
    k_scan1<<<NBLK, 256>>>();
    k_scan2<<<1, 256>>>();
    k_scan3<<<NBLK, 256>>>();
    k_fillinit<<<NBLK, 256>>>();
    k_fill<<<eb, 256>>>(src, dst, Ecnt);

    // layer 1: xw = x@W1 ; h1 = relu(agg(xw) + b1)
    gemm_k<<<(NN + 63) / 64, 256>>>(x, W1, g_xw, NN, FIN);
    agg_k<<<(NN + 7) / 8, 256>>>(g_xw, b1, g_h1, 1);

    // layer 2: hw = h1@W2 ; emb = agg(hw) + b2
    gemm_k<<<(NN + 63) / 64, 256>>>(g_h1, W2, g_hw, NN, HD);
    agg_k<<<(NN + 7) / 8, 256>>>(g_hw, b2, emb, 0);

    // pooled head
    pool_k<<<(GG + 7) / 8, 256>>>(emb, Wl, bl, out);
}